// round 4
// baseline (speedup 1.0000x reference)
#include <cuda_runtime.h>
#include <cuda_bf16.h>
#include <cstdint>

// ------------------------- scratch (device globals) -------------------------
__device__ float    g_p2[8 * 128 * 4096];          // pooled features (16 MB)
__device__ float    g_Gpart[16 * 8 * 128 * 128];   // Gram partials (8 MB)
__device__ float    g_sim[8 * 128 * 128];          // softmaxed sim
__device__ unsigned g_Mhi[8 * 64 * 128];           // M = sim^T, bf16 k-pair, hi
__device__ unsigned g_Mlo[8 * 64 * 128];           // residual (lo)

__device__ __forceinline__ unsigned pack_bf2(float e, float o) {
    unsigned short ue = __bfloat16_as_ushort(__float2bfloat16_rn(e));
    unsigned short uo = __bfloat16_as_ushort(__float2bfloat16_rn(o));
    return (unsigned)ue | ((unsigned)uo << 16);
}

// ------------------- k1: fused (dwconv3x3 s2 -> BN -> PReLU) x2 -------------
// grid.x = 1024 (b*128+c), grid.y = 4 (2x2 tiles of 32x32 p2), 256 threads.
#define XS_H 131
#define XS_W 132
#define P1_W 66

__global__ __launch_bounds__(256) void k1_pool(
    const float* __restrict__ x,
    const float* __restrict__ w1, const float* __restrict__ g1, const float* __restrict__ b1,
    const float* __restrict__ m1, const float* __restrict__ v1, const float* __restrict__ a1_,
    const float* __restrict__ w2, const float* __restrict__ g2, const float* __restrict__ b2,
    const float* __restrict__ m2, const float* __restrict__ v2, const float* __restrict__ a2_)
{
    extern __shared__ float sm1[];
    float* xs  = sm1;                 // [131][132]
    float* p1s = sm1 + XS_H * XS_W;   // [65][66]

    int bc  = blockIdx.x;
    int c   = bc & 127;
    int tid = threadIdx.x;
    int ty  = blockIdx.y >> 1, tx = blockIdx.y & 1;
    int oy  = ty * 32, ox = tx * 32;  // p2-tile origin

    float w1r[9], w2r[9];
#pragma unroll
    for (int i = 0; i < 9; i++) { w1r[i] = w1[c * 9 + i]; w2r[i] = w2[c * 9 + i]; }
    float s1 = g1[c] * rsqrtf(v1[c] + 1e-5f);
    float t1 = b1[c] - m1[c] * s1;
    float al1 = a1_[c];
    float s2 = g2[c] * rsqrtf(v2[c] + 1e-5f);
    float t2 = b2[c] - m2[c] * s2;
    float al2 = a2_[c];

    const float* xc = x + (size_t)bc * 65536;
    int gr0 = 4 * oy - 3, gc0 = 4 * ox - 3;
    for (int idx = tid; idx < XS_H * 131; idx += 256) {
        int r = idx / 131, cc = idx % 131;
        int gr = gr0 + r, gc = gc0 + cc;
        float v = 0.f;
        if ((unsigned)gr < 256u && (unsigned)gc < 256u) v = xc[gr * 256 + gc];
        xs[r * XS_W + cc] = v;
    }
    __syncthreads();

    // p1 tile 65x65; zero OUTSIDE the valid 128x128 p1 domain (conv2 padding)
    for (int idx = tid; idx < 65 * 65; idx += 256) {
        int j = idx / 65, i = idx % 65;
        int r1 = 2 * oy - 1 + j, c1 = 2 * ox - 1 + i;
        float v = 0.f;
        if ((unsigned)r1 < 128u && (unsigned)c1 < 128u) {
            const float* xr = xs + (2 * j) * XS_W + 2 * i;
            float acc = 0.f;
#pragma unroll
            for (int dy = 0; dy < 3; dy++)
#pragma unroll
                for (int dx = 0; dx < 3; dx++)
                    acc += w1r[dy * 3 + dx] * xr[dy * XS_W + dx];
            v = acc * s1 + t1;
            v = v > 0.f ? v : al1 * v;
        }
        p1s[j * P1_W + i] = v;
    }
    __syncthreads();

    float* outp = g_p2 + (size_t)bc * 4096;
    for (int idx = tid; idx < 32 * 32; idx += 256) {
        int j = idx >> 5, i = idx & 31;
        const float* pr = p1s + (2 * j) * P1_W + 2 * i;
        float acc = 0.f;
#pragma unroll
        for (int dy = 0; dy < 3; dy++)
#pragma unroll
            for (int dx = 0; dx < 3; dx++)
                acc += w2r[dy * 3 + dx] * pr[dy * P1_W + dx];
        float v = acc * s2 + t2;
        v = v > 0.f ? v : al2 * v;
        outp[(oy + j) * 64 + (ox + i)] = v;
    }
}

// ------------------- k2: Gram partials over n-chunks of 256 -----------------
// grid = 128 (chunk*8+b), 256 threads, 8x8 per-thread tile of 128x128.
#define PS_STRIDE 136

__global__ __launch_bounds__(256) void k2_gram()
{
    extern __shared__ float ps[]; // [256][136], transposed: ps[n][c]
    int b  = blockIdx.x & 7;
    int ch = blockIdx.x >> 3;
    int n0 = ch * 256;
    int tid = threadIdx.x;
    const float* pb = g_p2 + (size_t)b * 128 * 4096;

    for (int v = tid; v < 128 * 64; v += 256) {
        int c = v >> 6, q = (v & 63) << 2;
        float4 f = *(const float4*)(pb + c * 4096 + n0 + q);
        ps[(q + 0) * PS_STRIDE + c] = f.x;
        ps[(q + 1) * PS_STRIDE + c] = f.y;
        ps[(q + 2) * PS_STRIDE + c] = f.z;
        ps[(q + 3) * PS_STRIDE + c] = f.w;
    }
    __syncthreads();

    int tk = tid & 15, tc = tid >> 4;
    int cb = tc * 8, kb = tk * 8;
    float acc[8][8];
#pragma unroll
    for (int i = 0; i < 8; i++)
#pragma unroll
        for (int j = 0; j < 8; j++) acc[i][j] = 0.f;

    for (int n = 0; n < 256; n++) {
        const float* row = ps + n * PS_STRIDE;
        float4 A0 = *(const float4*)(row + cb);
        float4 A1 = *(const float4*)(row + cb + 4);
        float4 B0 = *(const float4*)(row + kb);
        float4 B1 = *(const float4*)(row + kb + 4);
        float a[8]  = {A0.x, A0.y, A0.z, A0.w, A1.x, A1.y, A1.z, A1.w};
        float bb[8] = {B0.x, B0.y, B0.z, B0.w, B1.x, B1.y, B1.z, B1.w};
#pragma unroll
        for (int i = 0; i < 8; i++)
#pragma unroll
            for (int j = 0; j < 8; j++)
                acc[i][j] += a[i] * bb[j];
    }

    float* gp = g_Gpart + ((size_t)(ch * 8 + b) * 128) * 128;
#pragma unroll
    for (int i = 0; i < 8; i++) {
        float4 o0 = {acc[i][0], acc[i][1], acc[i][2], acc[i][3]};
        float4 o1 = {acc[i][4], acc[i][5], acc[i][6], acc[i][7]};
        *(float4*)(gp + (cb + i) * 128 + kb)     = o0;
        *(float4*)(gp + (cb + i) * 128 + kb + 4) = o1;
    }
}

// ------------------- k3: reduce partials + row softmax ----------------------
__global__ __launch_bounds__(256) void k3_softmax()
{
    int b    = blockIdx.x;
    int c    = blockIdx.y * 8 + (threadIdx.x >> 5);
    int lane = threadIdx.x & 31;
    float4 acc = make_float4(0.f, 0.f, 0.f, 0.f);
    for (int ch = 0; ch < 16; ch++) {
        float4 g = *(const float4*)(g_Gpart + ((size_t)(ch * 8 + b) * 128 + c) * 128 + lane * 4);
        acc.x += g.x; acc.y += g.y; acc.z += g.z; acc.w += g.w;
    }
    const float s = 0.015625f;  // 4096^-0.5
    float lx = acc.x * s, ly = acc.y * s, lz = acc.z * s, lw = acc.w * s;
    float mx = fmaxf(fmaxf(lx, ly), fmaxf(lz, lw));
#pragma unroll
    for (int o = 16; o; o >>= 1) mx = fmaxf(mx, __shfl_xor_sync(0xffffffffu, mx, o));
    float ex = expf(lx - mx), ey = expf(ly - mx), ez = expf(lz - mx), ew = expf(lw - mx);
    float sum = ex + ey + ez + ew;
#pragma unroll
    for (int o = 16; o; o >>= 1) sum += __shfl_xor_sync(0xffffffffu, sum, o);
    float inv = 1.0f / sum;
    float4 o4 = make_float4(ex * inv, ey * inv, ez * inv, ew * inv);
    *(float4*)(g_sim + ((size_t)b * 128 + c) * 128 + lane * 4) = o4;
}

// ------------------- k3b: pack M = sim^T into mma A-fragment words ----------
__global__ __launch_bounds__(256) void k3b_pack()
{
    int b    = blockIdx.x;
    int base = blockIdx.y * 16;
    for (int idx = threadIdx.x; idx < 16 * 128; idx += 256) {
        int kh = base + (idx >> 7), m = idx & 127;
        float s0 = g_sim[((size_t)b * 128 + 2 * kh)     * 128 + m];
        float s1 = g_sim[((size_t)b * 128 + 2 * kh + 1) * 128 + m];
        __nv_bfloat16 h0 = __float2bfloat16_rn(s0);
        __nv_bfloat16 h1 = __float2bfloat16_rn(s1);
        unsigned hi = (unsigned)__bfloat16_as_ushort(h0) |
                      ((unsigned)__bfloat16_as_ushort(h1) << 16);
        unsigned lo = pack_bf2(s0 - __bfloat162float(h0), s1 - __bfloat162float(h1));
        g_Mhi[((size_t)b * 64 + kh) * 128 + m] = hi;
        g_Mlo[((size_t)b * 64 + kh) * 128 + m] = lo;
    }
}

// ------------------- k4: out[b] = M @ X via split-bf16 mma.sync -------------
// 144 CTAs = 8 b x 18 slices, 512 thr (16 warps 4x4, 32x32 warp tile).
#define KH_STRIDE 136
#define MS_WORDS  (64 * KH_STRIDE)

#define MMA_BF16(d, a, bfr)                                            \
    asm volatile(                                                      \
        "mma.sync.aligned.m16n8k16.row.col.f32.bf16.bf16.f32 "         \
        "{%0,%1,%2,%3}, {%4,%5,%6,%7}, {%8,%9}, {%0,%1,%2,%3};"        \
        : "+f"(d[0]), "+f"(d[1]), "+f"(d[2]), "+f"(d[3])               \
        : "r"(a[0]), "r"(a[1]), "r"(a[2]), "r"(a[3]),                  \
          "r"(bfr[0]), "r"(bfr[1]))

__global__ __launch_bounds__(512, 1) void k4_gemm(const float* __restrict__ x,
                                                  float* __restrict__ out)
{
    extern __shared__ unsigned smu[];
    unsigned* Mh = smu;
    unsigned* Ml = smu + MS_WORDS;
    unsigned* Xh = smu + 2 * MS_WORDS;
    unsigned* Xl = smu + 3 * MS_WORDS;

    int b     = blockIdx.x & 7;
    int slice = blockIdx.x >> 3;  // 0..17
    int tid   = threadIdx.x;

    for (int idx = tid; idx < 8192; idx += 512) {
        int kh = idx >> 7, m = idx & 127;
        Mh[kh * KH_STRIDE + m] = g_Mhi[(size_t)b * 8192 + idx];
        Ml[kh * KH_STRIDE + m] = g_Mlo[(size_t)b * 8192 + idx];
    }

    const float* xb = x   + (size_t)b * 128 * 65536;
    float*       ob = out + (size_t)b * 128 * 65536;

    int khs  = tid >> 3;          // staged row pair 0..63
    int nseg = (tid & 7) << 4;    // staged n offset
    int w    = tid >> 5;
    int lane = tid & 31;
    int wm = (w & 3) * 32, wn = (w >> 2) * 32;
    int l4 = lane >> 2, lm = lane & 3;

    float4 r0[4], r1[4];
    int t = slice;
    {
        const float* p0 = xb + (size_t)(2 * khs) * 65536 + t * 128 + nseg;
        const float* p1 = p0 + 65536;
#pragma unroll
        for (int j = 0; j < 4; j++) { r0[j] = *(const float4*)(p0 + 4 * j);
                                      r1[j] = *(const float4*)(p1 + 4 * j); }
    }

    for (; t < 512; t += 18) {
        unsigned* dh = Xh + khs * KH_STRIDE + nseg;
        unsigned* dl = Xl + khs * KH_STRIDE + nseg;
#pragma unroll
        for (int j = 0; j < 4; j++) {
            const float* e0 = (const float*)&r0[j];
            const float* e1 = (const float*)&r1[j];
#pragma unroll
            for (int e = 0; e < 4; e++) {
                float xa = e0[e], xc = e1[e];
                __nv_bfloat16 ha = __float2bfloat16_rn(xa);
                __nv_bfloat16 hb = __float2bfloat16_rn(xc);
                dh[4 * j + e] = (unsigned)__bfloat16_as_ushort(ha) |
                                ((unsigned)__bfloat16_as_ushort(hb) << 16);
                dl[4 * j + e] = pack_bf2(xa - __bfloat162float(ha),
                                         xc - __bfloat162float(hb));
            }
        }
        __syncthreads();

        if (t + 18 < 512) {  // prefetch next X tile (LDGs fly over MMA section)
            const float* p0 = xb + (size_t)(2 * khs) * 65536 + (t + 18) * 128 + nseg;
            const float* p1 = p0 + 65536;
#pragma unroll
            for (int j = 0; j < 4; j++) { r0[j] = *(const float4*)(p0 + 4 * j);
                                          r1[j] = *(const float4*)(p1 + 4 * j); }
        }

        float acc[2][4][4];
#pragma unroll
        for (int mi = 0; mi < 2; mi++)
#pragma unroll
            for (int ni = 0; ni < 4; ni++)
#pragma unroll
                for (int e = 0; e < 4; e++) acc[mi][ni][e] = 0.f;

#pragma unroll
        for (int ks = 0; ks < 8; ks++) {
            int r0a = (ks * 8 + lm) * KH_STRIDE;
            int r1a = r0a + 4 * KH_STRIDE;
            unsigned ah[2][4], al_[2][4];
#pragma unroll
            for (int mi = 0; mi < 2; mi++) {
                int colA = wm + 16 * mi + l4;
                ah[mi][0]  = Mh[r0a + colA];  ah[mi][1]  = Mh[r0a + colA + 8];
                ah[mi][2]  = Mh[r1a + colA];  ah[mi][3]  = Mh[r1a + colA + 8];
                al_[mi][0] = Ml[r0a + colA];  al_[mi][1] = Ml[r0a + colA + 8];
                al_[mi][2] = Ml[r1a + colA];  al_[mi][3] = Ml[r1a + colA + 8];
            }
            unsigned bh[4][2], bl[4][2];
#pragma unroll
            for (int ni = 0; ni < 4; ni++) {
                int colB = wn + 8 * ni + l4;
                bh[ni][0] = Xh[r0a + colB];  bh[ni][1] = Xh[r1a + colB];
                bl[ni][0] = Xl[r0a + colB];  bl[ni][1] = Xl[r1a + colB];
            }
#pragma unroll
            for (int mi = 0; mi < 2; mi++)
#pragma unroll
                for (int ni = 0; ni < 4; ni++) {
                    MMA_BF16(acc[mi][ni], ah[mi],  bh[ni]);
                    MMA_BF16(acc[mi][ni], al_[mi], bh[ni]);
                    MMA_BF16(acc[mi][ni], ah[mi],  bl[ni]);
                }
        }

#pragma unroll
        for (int mi = 0; mi < 2; mi++) {
            int row = wm + 16 * mi + l4;
#pragma unroll
            for (int ni = 0; ni < 4; ni++) {
                int col = t * 128 + wn + 8 * ni + 2 * lm;
                float2 v0 = {acc[mi][ni][0], acc[mi][ni][1]};
                float2 v1 = {acc[mi][ni][2], acc[mi][ni][3]};
                *(float2*)(ob + (size_t)row * 65536 + col)       = v0;
                *(float2*)(ob + (size_t)(row + 8) * 65536 + col) = v1;
            }
        }
        __syncthreads();
    }
}

// ---------------------------------------------------------------------------
extern "C" void kernel_launch(void* const* d_in, const int* in_sizes, int n_in,
                              void* d_out, int out_size)
{
    const float* x  = (const float*)d_in[0];
    const float* w1 = (const float*)d_in[1];
    const float* g1 = (const float*)d_in[2];
    const float* b1 = (const float*)d_in[3];
    const float* m1 = (const float*)d_in[4];
    const float* v1 = (const float*)d_in[5];
    const float* a1 = (const float*)d_in[6];
    const float* w2 = (const float*)d_in[7];
    const float* g2 = (const float*)d_in[8];
    const float* b2 = (const float*)d_in[9];
    const float* m2 = (const float*)d_in[10];
    const float* v2 = (const float*)d_in[11];
    const float* a2 = (const float*)d_in[12];
    float* out = (float*)d_out;

    const int SM1 = (XS_H * XS_W + 65 * P1_W) * 4;   // 86328
    const int SM2 = 256 * PS_STRIDE * 4;             // 139264
    const int SM4 = 4 * MS_WORDS * 4;                // 139264
    static bool attr_done = false;
    if (!attr_done) {
        cudaFuncSetAttribute(k1_pool, cudaFuncAttributeMaxDynamicSharedMemorySize, SM1);
        cudaFuncSetAttribute(k2_gram, cudaFuncAttributeMaxDynamicSharedMemorySize, SM2);
        cudaFuncSetAttribute(k4_gemm, cudaFuncAttributeMaxDynamicSharedMemorySize, SM4);
        attr_done = true;
    }

    k1_pool<<<dim3(1024, 4), 256, SM1>>>(x, w1, g1, b1, m1, v1, a1,
                                         w2, g2, b2, m2, v2, a2);
    k2_gram<<<128, 256, SM2>>>();
    k3_softmax<<<dim3(8, 16), 256>>>();
    k3b_pack<<<dim3(8, 4), 256>>>();
    k4_gemm<<<144, 512, SM4>>>(x, out);
}

// round 6
// speedup vs baseline: 1.0178x; 1.0178x over previous
#include <cuda_runtime.h>
#include <cuda_bf16.h>
#include <cstdint>

// ------------------------- scratch (device globals) -------------------------
__device__ float    g_p2[8 * 128 * 4096];          // pooled features (16 MB)
__device__ float    g_Gpart[16 * 8 * 128 * 128];   // Gram partials (8 MB)
__device__ float    g_sim[8 * 128 * 128];          // softmaxed sim
__device__ unsigned g_Mhi[8 * 64 * 128];           // M = sim^T, bf16 k-pair, hi
__device__ unsigned g_Mlo[8 * 64 * 128];           // residual (lo)

__device__ __forceinline__ unsigned pack_bf2(float e, float o) {
    unsigned short ue = __bfloat16_as_ushort(__float2bfloat16_rn(e));
    unsigned short uo = __bfloat16_as_ushort(__float2bfloat16_rn(o));
    return (unsigned)ue | ((unsigned)uo << 16);
}

// ------------------- k1: fused (dwconv3x3 s2 -> BN -> PReLU) x2 -------------
// grid.x = 1024 (b*128+c), grid.y = 4 (2x2 tiles of 32x32 p2), 256 threads.
#define XS_H 131
#define XS_W 132
#define P1_W 66

__global__ __launch_bounds__(256) void k1_pool(
    const float* __restrict__ x,
    const float* __restrict__ w1, const float* __restrict__ g1, const float* __restrict__ b1,
    const float* __restrict__ m1, const float* __restrict__ v1, const float* __restrict__ a1_,
    const float* __restrict__ w2, const float* __restrict__ g2, const float* __restrict__ b2,
    const float* __restrict__ m2, const float* __restrict__ v2, const float* __restrict__ a2_)
{
    extern __shared__ float sm1[];
    float* xs  = sm1;                 // [131][132]
    float* p1s = sm1 + XS_H * XS_W;   // [65][66]

    int bc  = blockIdx.x;
    int c   = bc & 127;
    int tid = threadIdx.x;
    int ty  = blockIdx.y >> 1, tx = blockIdx.y & 1;
    int oy  = ty * 32, ox = tx * 32;  // p2-tile origin

    float w1r[9], w2r[9];
#pragma unroll
    for (int i = 0; i < 9; i++) { w1r[i] = w1[c * 9 + i]; w2r[i] = w2[c * 9 + i]; }
    float s1 = g1[c] * rsqrtf(v1[c] + 1e-5f);
    float t1 = b1[c] - m1[c] * s1;
    float al1 = a1_[c];
    float s2 = g2[c] * rsqrtf(v2[c] + 1e-5f);
    float t2 = b2[c] - m2[c] * s2;
    float al2 = a2_[c];

    const float* xc = x + (size_t)bc * 65536;
    int gr0 = 4 * oy - 3, gc0 = 4 * ox - 3;
    for (int idx = tid; idx < XS_H * 131; idx += 256) {
        int r = idx / 131, cc = idx % 131;
        int gr = gr0 + r, gc = gc0 + cc;
        float v = 0.f;
        if ((unsigned)gr < 256u && (unsigned)gc < 256u) v = xc[gr * 256 + gc];
        xs[r * XS_W + cc] = v;
    }
    __syncthreads();

    // p1 tile 65x65; zero OUTSIDE the valid 128x128 p1 domain (conv2 padding)
    for (int idx = tid; idx < 65 * 65; idx += 256) {
        int j = idx / 65, i = idx % 65;
        int r1 = 2 * oy - 1 + j, c1 = 2 * ox - 1 + i;
        float v = 0.f;
        if ((unsigned)r1 < 128u && (unsigned)c1 < 128u) {
            const float* xr = xs + (2 * j) * XS_W + 2 * i;
            float acc = 0.f;
#pragma unroll
            for (int dy = 0; dy < 3; dy++)
#pragma unroll
                for (int dx = 0; dx < 3; dx++)
                    acc += w1r[dy * 3 + dx] * xr[dy * XS_W + dx];
            v = acc * s1 + t1;
            v = v > 0.f ? v : al1 * v;
        }
        p1s[j * P1_W + i] = v;
    }
    __syncthreads();

    float* outp = g_p2 + (size_t)bc * 4096;
    for (int idx = tid; idx < 32 * 32; idx += 256) {
        int j = idx >> 5, i = idx & 31;
        const float* pr = p1s + (2 * j) * P1_W + 2 * i;
        float acc = 0.f;
#pragma unroll
        for (int dy = 0; dy < 3; dy++)
#pragma unroll
            for (int dx = 0; dx < 3; dx++)
                acc += w2r[dy * 3 + dx] * pr[dy * P1_W + dx];
        float v = acc * s2 + t2;
        v = v > 0.f ? v : al2 * v;
        outp[(oy + j) * 64 + (ox + i)] = v;
    }
}

// ------------------- k2: Gram partials over n-chunks of 256 -----------------
// grid = 128 (chunk*8+b), 256 threads, 8x8 per-thread tile of 128x128.
#define PS_STRIDE 136

__global__ __launch_bounds__(256) void k2_gram()
{
    extern __shared__ float ps[]; // [256][136], transposed: ps[n][c]
    int b  = blockIdx.x & 7;
    int ch = blockIdx.x >> 3;
    int n0 = ch * 256;
    int tid = threadIdx.x;
    const float* pb = g_p2 + (size_t)b * 128 * 4096;

    for (int v = tid; v < 128 * 64; v += 256) {
        int c = v >> 6, q = (v & 63) << 2;
        float4 f = *(const float4*)(pb + c * 4096 + n0 + q);
        ps[(q + 0) * PS_STRIDE + c] = f.x;
        ps[(q + 1) * PS_STRIDE + c] = f.y;
        ps[(q + 2) * PS_STRIDE + c] = f.z;
        ps[(q + 3) * PS_STRIDE + c] = f.w;
    }
    __syncthreads();

    int tk = tid & 15, tc = tid >> 4;
    int cb = tc * 8, kb = tk * 8;
    float acc[8][8];
#pragma unroll
    for (int i = 0; i < 8; i++)
#pragma unroll
        for (int j = 0; j < 8; j++) acc[i][j] = 0.f;

    for (int n = 0; n < 256; n++) {
        const float* row = ps + n * PS_STRIDE;
        float4 A0 = *(const float4*)(row + cb);
        float4 A1 = *(const float4*)(row + cb + 4);
        float4 B0 = *(const float4*)(row + kb);
        float4 B1 = *(const float4*)(row + kb + 4);
        float a[8]  = {A0.x, A0.y, A0.z, A0.w, A1.x, A1.y, A1.z, A1.w};
        float bb[8] = {B0.x, B0.y, B0.z, B0.w, B1.x, B1.y, B1.z, B1.w};
#pragma unroll
        for (int i = 0; i < 8; i++)
#pragma unroll
            for (int j = 0; j < 8; j++)
                acc[i][j] += a[i] * bb[j];
    }

    float* gp = g_Gpart + ((size_t)(ch * 8 + b) * 128) * 128;
#pragma unroll
    for (int i = 0; i < 8; i++) {
        float4 o0 = {acc[i][0], acc[i][1], acc[i][2], acc[i][3]};
        float4 o1 = {acc[i][4], acc[i][5], acc[i][6], acc[i][7]};
        *(float4*)(gp + (cb + i) * 128 + kb)     = o0;
        *(float4*)(gp + (cb + i) * 128 + kb + 4) = o1;
    }
}

// ------------------- k3: reduce partials + row softmax ----------------------
__global__ __launch_bounds__(256) void k3_softmax()
{
    int b    = blockIdx.x;
    int c    = blockIdx.y * 8 + (threadIdx.x >> 5);
    int lane = threadIdx.x & 31;
    float4 acc = make_float4(0.f, 0.f, 0.f, 0.f);
    for (int ch = 0; ch < 16; ch++) {
        float4 g = *(const float4*)(g_Gpart + ((size_t)(ch * 8 + b) * 128 + c) * 128 + lane * 4);
        acc.x += g.x; acc.y += g.y; acc.z += g.z; acc.w += g.w;
    }
    const float s = 0.015625f;  // 4096^-0.5
    float lx = acc.x * s, ly = acc.y * s, lz = acc.z * s, lw = acc.w * s;
    float mx = fmaxf(fmaxf(lx, ly), fmaxf(lz, lw));
#pragma unroll
    for (int o = 16; o; o >>= 1) mx = fmaxf(mx, __shfl_xor_sync(0xffffffffu, mx, o));
    float ex = expf(lx - mx), ey = expf(ly - mx), ez = expf(lz - mx), ew = expf(lw - mx);
    float sum = ex + ey + ez + ew;
#pragma unroll
    for (int o = 16; o; o >>= 1) sum += __shfl_xor_sync(0xffffffffu, sum, o);
    float inv = 1.0f / sum;
    float4 o4 = make_float4(ex * inv, ey * inv, ez * inv, ew * inv);
    *(float4*)(g_sim + ((size_t)b * 128 + c) * 128 + lane * 4) = o4;
}

// ------------------- k3b: pack M = sim^T into mma A-fragment words ----------
__global__ __launch_bounds__(256) void k3b_pack()
{
    int b    = blockIdx.x;
    int base = blockIdx.y * 16;
    for (int idx = threadIdx.x; idx < 16 * 128; idx += 256) {
        int kh = base + (idx >> 7), m = idx & 127;
        float s0 = g_sim[((size_t)b * 128 + 2 * kh)     * 128 + m];
        float s1 = g_sim[((size_t)b * 128 + 2 * kh + 1) * 128 + m];
        __nv_bfloat16 h0 = __float2bfloat16_rn(s0);
        __nv_bfloat16 h1 = __float2bfloat16_rn(s1);
        unsigned hi = (unsigned)__bfloat16_as_ushort(h0) |
                      ((unsigned)__bfloat16_as_ushort(h1) << 16);
        unsigned lo = pack_bf2(s0 - __bfloat162float(h0), s1 - __bfloat162float(h1));
        g_Mhi[((size_t)b * 64 + kh) * 128 + m] = hi;
        g_Mlo[((size_t)b * 64 + kh) * 128 + m] = lo;
    }
}

// ------------------- k4: out[b] = M @ X via split-bf16 mma.sync -------------
// 144 CTAs = 8 b x 18 slices, 512 thr (16 warps 4x4, 32x32 warp tile).
#define KH_STRIDE 136
#define MS_WORDS  (64 * KH_STRIDE)

#define MMA_BF16(d, a, bfr)                                            \
    asm volatile(                                                      \
        "mma.sync.aligned.m16n8k16.row.col.f32.bf16.bf16.f32 "         \
        "{%0,%1,%2,%3}, {%4,%5,%6,%7}, {%8,%9}, {%0,%1,%2,%3};"        \
        : "+f"(d[0]), "+f"(d[1]), "+f"(d[2]), "+f"(d[3])               \
        : "r"(a[0]), "r"(a[1]), "r"(a[2]), "r"(a[3]),                  \
          "r"(bfr[0]), "r"(bfr[1]))

__global__ __launch_bounds__(512, 1) void k4_gemm(const float* __restrict__ x,
                                                  float* __restrict__ out)
{
    extern __shared__ unsigned smu[];
    unsigned* Mh = smu;
    unsigned* Ml = smu + MS_WORDS;
    unsigned* Xh = smu + 2 * MS_WORDS;
    unsigned* Xl = smu + 3 * MS_WORDS;

    int b     = blockIdx.x & 7;
    int slice = blockIdx.x >> 3;  // 0..17
    int tid   = threadIdx.x;

    for (int idx = tid; idx < 8192; idx += 512) {
        int kh = idx >> 7, m = idx & 127;
        Mh[kh * KH_STRIDE + m] = g_Mhi[(size_t)b * 8192 + idx];
        Ml[kh * KH_STRIDE + m] = g_Mlo[(size_t)b * 8192 + idx];
    }

    const float* xb = x   + (size_t)b * 128 * 65536;
    float*       ob = out + (size_t)b * 128 * 65536;

    int khs  = tid >> 3;          // staged row pair 0..63
    int nseg = (tid & 7) << 4;    // staged n offset
    int w    = tid >> 5;
    int lane = tid & 31;
    int wm = (w & 3) * 32, wn = (w >> 2) * 32;
    int l4 = lane >> 2, lm = lane & 3;

    float4 r0[4], r1[4];
    int t = slice;
    {
        const float* p0 = xb + (size_t)(2 * khs) * 65536 + t * 128 + nseg;
        const float* p1 = p0 + 65536;
#pragma unroll
        for (int j = 0; j < 4; j++) { r0[j] = *(const float4*)(p0 + 4 * j);
                                      r1[j] = *(const float4*)(p1 + 4 * j); }
    }

    for (; t < 512; t += 18) {
        unsigned* dh = Xh + khs * KH_STRIDE + nseg;
        unsigned* dl = Xl + khs * KH_STRIDE + nseg;
#pragma unroll
        for (int j = 0; j < 4; j++) {
            const float* e0 = (const float*)&r0[j];
            const float* e1 = (const float*)&r1[j];
#pragma unroll
            for (int e = 0; e < 4; e++) {
                float xa = e0[e], xc = e1[e];
                __nv_bfloat16 ha = __float2bfloat16_rn(xa);
                __nv_bfloat16 hb = __float2bfloat16_rn(xc);
                dh[4 * j + e] = (unsigned)__bfloat16_as_ushort(ha) |
                                ((unsigned)__bfloat16_as_ushort(hb) << 16);
                dl[4 * j + e] = pack_bf2(xa - __bfloat162float(ha),
                                         xc - __bfloat162float(hb));
            }
        }
        __syncthreads();

        if (t + 18 < 512) {  // prefetch next X tile (LDGs fly over MMA section)
            const float* p0 = xb + (size_t)(2 * khs) * 65536 + (t + 18) * 128 + nseg;
            const float* p1 = p0 + 65536;
#pragma unroll
            for (int j = 0; j < 4; j++) { r0[j] = *(const float4*)(p0 + 4 * j);
                                          r1[j] = *(const float4*)(p1 + 4 * j); }
        }

        float acc[2][4][4];
#pragma unroll
        for (int mi = 0; mi < 2; mi++)
#pragma unroll
            for (int ni = 0; ni < 4; ni++)
#pragma unroll
                for (int e = 0; e < 4; e++) acc[mi][ni][e] = 0.f;

#pragma unroll
        for (int ks = 0; ks < 8; ks++) {
            int r0a = (ks * 8 + lm) * KH_STRIDE;
            int r1a = r0a + 4 * KH_STRIDE;
            unsigned ah[2][4], al_[2][4];
#pragma unroll
            for (int mi = 0; mi < 2; mi++) {
                int colA = wm + 16 * mi + l4;
                ah[mi][0]  = Mh[r0a + colA];  ah[mi][1]  = Mh[r0a + colA + 8];
                ah[mi][2]  = Mh[r1a + colA];  ah[mi][3]  = Mh[r1a + colA + 8];
                al_[mi][0] = Ml[r0a + colA];  al_[mi][1] = Ml[r0a + colA + 8];
                al_[mi][2] = Ml[r1a + colA];  al_[mi][3] = Ml[r1a + colA + 8];
            }
            unsigned bh[4][2], bl[4][2];
#pragma unroll
            for (int ni = 0; ni < 4; ni++) {
                int colB = wn + 8 * ni + l4;
                bh[ni][0] = Xh[r0a + colB];  bh[ni][1] = Xh[r1a + colB];
                bl[ni][0] = Xl[r0a + colB];  bl[ni][1] = Xl[r1a + colB];
            }
#pragma unroll
            for (int mi = 0; mi < 2; mi++)
#pragma unroll
                for (int ni = 0; ni < 4; ni++) {
                    MMA_BF16(acc[mi][ni], ah[mi],  bh[ni]);
                    MMA_BF16(acc[mi][ni], al_[mi], bh[ni]);
                    MMA_BF16(acc[mi][ni], ah[mi],  bl[ni]);
                }
        }

#pragma unroll
        for (int mi = 0; mi < 2; mi++) {
            int row = wm + 16 * mi + l4;
#pragma unroll
            for (int ni = 0; ni < 4; ni++) {
                int col = t * 128 + wn + 8 * ni + 2 * lm;
                float2 v0 = {acc[mi][ni][0], acc[mi][ni][1]};
                float2 v1 = {acc[mi][ni][2], acc[mi][ni][3]};
                *(float2*)(ob + (size_t)row * 65536 + col)       = v0;
                *(float2*)(ob + (size_t)(row + 8) * 65536 + col) = v1;
            }
        }
        __syncthreads();
    }
}

// ---------------------------------------------------------------------------
extern "C" void kernel_launch(void* const* d_in, const int* in_sizes, int n_in,
                              void* d_out, int out_size)
{
    const float* x  = (const float*)d_in[0];
    const float* w1 = (const float*)d_in[1];
    const float* g1 = (const float*)d_in[2];
    const float* b1 = (const float*)d_in[3];
    const float* m1 = (const float*)d_in[4];
    const float* v1 = (const float*)d_in[5];
    const float* a1 = (const float*)d_in[6];
    const float* w2 = (const float*)d_in[7];
    const float* g2 = (const float*)d_in[8];
    const float* b2 = (const float*)d_in[9];
    const float* m2 = (const float*)d_in[10];
    const float* v2 = (const float*)d_in[11];
    const float* a2 = (const float*)d_in[12];
    float* out = (float*)d_out;

    const int SM1 = (XS_H * XS_W + 65 * P1_W) * 4;   // 86328
    const int SM2 = 256 * PS_STRIDE * 4;             // 139264
    const int SM4 = 4 * MS_WORDS * 4;                // 139264
    static bool attr_done = false;
    if (!attr_done) {
        cudaFuncSetAttribute(k1_pool, cudaFuncAttributeMaxDynamicSharedMemorySize, SM1);
        cudaFuncSetAttribute(k2_gram, cudaFuncAttributeMaxDynamicSharedMemorySize, SM2);
        cudaFuncSetAttribute(k4_gemm, cudaFuncAttributeMaxDynamicSharedMemorySize, SM4);
        attr_done = true;
    }

    k1_pool<<<dim3(1024, 4), 256, SM1>>>(x, w1, g1, b1, m1, v1, a1,
                                         w2, g2, b2, m2, v2, a2);
    k2_gram<<<128, 256, SM2>>>();
    k3_softmax<<<dim3(8, 16), 256>>>();
    k3b_pack<<<dim3(8, 4), 256>>>();
    k4_gemm<<<144, 512, SM4>>>(x, out);
}

// round 11
// speedup vs baseline: 1.1455x; 1.1254x over previous
#include <cuda_runtime.h>
#include <cuda_bf16.h>
#include <cuda_fp16.h>
#include <cstdint>

// scratch
__device__ float    g_p2[8 * 128 * 4096];
__device__ float    g_Gpart[16 * 8 * 128 * 128];
__device__ float    g_sim[8 * 128 * 128];
__device__ unsigned g_Mhi[8 * 64 * 128];   // M = sim^T, fp16 k-pair, hi
__device__ unsigned g_Mlo[8 * 64 * 128];   // fp16 residual (lo)

// ---- k1: fused (dwconv3x3 s2 -> BN -> PReLU) x2 ----
#define XS_H 131
#define XS_W 132
#define P1_W 66

__global__ __launch_bounds__(256) void k1_pool(
    const float* __restrict__ x,
    const float* __restrict__ w1, const float* __restrict__ g1, const float* __restrict__ b1,
    const float* __restrict__ m1, const float* __restrict__ v1, const float* __restrict__ a1_,
    const float* __restrict__ w2, const float* __restrict__ g2, const float* __restrict__ b2,
    const float* __restrict__ m2, const float* __restrict__ v2, const float* __restrict__ a2_)
{
    extern __shared__ float sm1[];
    float* xs  = sm1;
    float* p1s = sm1 + XS_H * XS_W;

    int bc = blockIdx.x, c = bc & 127, tid = threadIdx.x;
    int oy = (blockIdx.y >> 1) * 32, ox = (blockIdx.y & 1) * 32;

    float w1r[9], w2r[9];
#pragma unroll
    for (int i = 0; i < 9; i++) { w1r[i] = w1[c * 9 + i]; w2r[i] = w2[c * 9 + i]; }
    float s1 = g1[c] * rsqrtf(v1[c] + 1e-5f), t1 = b1[c] - m1[c] * s1, al1 = a1_[c];
    float s2 = g2[c] * rsqrtf(v2[c] + 1e-5f), t2 = b2[c] - m2[c] * s2, al2 = a2_[c];

    const float* xc = x + (size_t)bc * 65536;
    int gr0 = 4 * oy - 3, gc0 = 4 * ox - 3;
    for (int idx = tid; idx < XS_H * 131; idx += 256) {
        int r = idx / 131, cc = idx % 131;
        int gr = gr0 + r, gc = gc0 + cc;
        float v = 0.f;
        if ((unsigned)gr < 256u && (unsigned)gc < 256u) v = xc[gr * 256 + gc];
        xs[r * XS_W + cc] = v;
    }
    __syncthreads();

    for (int idx = tid; idx < 65 * 65; idx += 256) {
        int j = idx / 65, i = idx % 65;
        int r1 = 2 * oy - 1 + j, c1 = 2 * ox - 1 + i;
        float v = 0.f;
        if ((unsigned)r1 < 128u && (unsigned)c1 < 128u) {
            const float* xr = xs + (2 * j) * XS_W + 2 * i;
            float acc = 0.f;
#pragma unroll
            for (int dy = 0; dy < 3; dy++)
#pragma unroll
                for (int dx = 0; dx < 3; dx++)
                    acc += w1r[dy * 3 + dx] * xr[dy * XS_W + dx];
            v = acc * s1 + t1;
            v = v > 0.f ? v : al1 * v;
        }
        p1s[j * P1_W + i] = v;
    }
    __syncthreads();

    float* outp = g_p2 + (size_t)bc * 4096;
    for (int idx = tid; idx < 32 * 32; idx += 256) {
        int j = idx >> 5, i = idx & 31;
        const float* pr = p1s + (2 * j) * P1_W + 2 * i;
        float acc = 0.f;
#pragma unroll
        for (int dy = 0; dy < 3; dy++)
#pragma unroll
            for (int dx = 0; dx < 3; dx++)
                acc += w2r[dy * 3 + dx] * pr[dy * P1_W + dx];
        float v = acc * s2 + t2;
        v = v > 0.f ? v : al2 * v;
        outp[(oy + j) * 64 + (ox + i)] = v;
    }
}

// ---- k2: Gram partials ----
#define PS_STRIDE 136
__global__ __launch_bounds__(256) void k2_gram()
{
    extern __shared__ float ps[];
    int b = blockIdx.x & 7, ch = blockIdx.x >> 3, n0 = ch * 256, tid = threadIdx.x;
    const float* pb = g_p2 + (size_t)b * 128 * 4096;

    for (int v = tid; v < 128 * 64; v += 256) {
        int c = v >> 6, q = (v & 63) << 2;
        float4 f = *(const float4*)(pb + c * 4096 + n0 + q);
        ps[(q + 0) * PS_STRIDE + c] = f.x;
        ps[(q + 1) * PS_STRIDE + c] = f.y;
        ps[(q + 2) * PS_STRIDE + c] = f.z;
        ps[(q + 3) * PS_STRIDE + c] = f.w;
    }
    __syncthreads();

    int cb = (tid >> 4) * 8, kb = (tid & 15) * 8;
    float acc[8][8];
#pragma unroll
    for (int i = 0; i < 8; i++)
#pragma unroll
        for (int j = 0; j < 8; j++) acc[i][j] = 0.f;

    for (int n = 0; n < 256; n++) {
        const float* row = ps + n * PS_STRIDE;
        float4 A0 = *(const float4*)(row + cb), A1 = *(const float4*)(row + cb + 4);
        float4 B0 = *(const float4*)(row + kb), B1 = *(const float4*)(row + kb + 4);
        float a[8]  = {A0.x, A0.y, A0.z, A0.w, A1.x, A1.y, A1.z, A1.w};
        float bb[8] = {B0.x, B0.y, B0.z, B0.w, B1.x, B1.y, B1.z, B1.w};
#pragma unroll
        for (int i = 0; i < 8; i++)
#pragma unroll
            for (int j = 0; j < 8; j++) acc[i][j] += a[i] * bb[j];
    }
    float* gp = g_Gpart + ((size_t)(ch * 8 + b) * 128) * 128;
#pragma unroll
    for (int i = 0; i < 8; i++) {
        float4 o0 = {acc[i][0], acc[i][1], acc[i][2], acc[i][3]};
        float4 o1 = {acc[i][4], acc[i][5], acc[i][6], acc[i][7]};
        *(float4*)(gp + (cb + i) * 128 + kb)     = o0;
        *(float4*)(gp + (cb + i) * 128 + kb + 4) = o1;
    }
}

// ---- k3: reduce + softmax ----
__global__ __launch_bounds__(256) void k3_softmax()
{
    int b = blockIdx.x, c = blockIdx.y * 8 + (threadIdx.x >> 5), lane = threadIdx.x & 31;
    float4 acc = make_float4(0.f, 0.f, 0.f, 0.f);
    for (int ch = 0; ch < 16; ch++) {
        float4 g = *(const float4*)(g_Gpart + ((size_t)(ch * 8 + b) * 128 + c) * 128 + lane * 4);
        acc.x += g.x; acc.y += g.y; acc.z += g.z; acc.w += g.w;
    }
    const float s = 0.015625f;
    float lx = acc.x * s, ly = acc.y * s, lz = acc.z * s, lw = acc.w * s;
    float mx = fmaxf(fmaxf(lx, ly), fmaxf(lz, lw));
#pragma unroll
    for (int o = 16; o; o >>= 1) mx = fmaxf(mx, __shfl_xor_sync(0xffffffffu, mx, o));
    float ex = expf(lx - mx), ey = expf(ly - mx), ez = expf(lz - mx), ew = expf(lw - mx);
    float sum = ex + ey + ez + ew;
#pragma unroll
    for (int o = 16; o; o >>= 1) sum += __shfl_xor_sync(0xffffffffu, sum, o);
    float inv = 1.0f / sum;
    float4 o4 = make_float4(ex * inv, ey * inv, ez * inv, ew * inv);
    *(float4*)(g_sim + ((size_t)b * 128 + c) * 128 + lane * 4) = o4;
}

// ---- k3b: pack M = sim^T into fp16 hi/lo mma A-fragment words ----
__global__ __launch_bounds__(256) void k3b_pack()
{
    int b = blockIdx.x, base = blockIdx.y * 16;
    for (int idx = threadIdx.x; idx < 16 * 128; idx += 256) {
        int kh = base + (idx >> 7), m = idx & 127;
        float s0 = g_sim[((size_t)b * 128 + 2 * kh)     * 128 + m];
        float s1 = g_sim[((size_t)b * 128 + 2 * kh + 1) * 128 + m];
        unsigned wh;  // lo = h(s0), hi = h(s1)
        asm("cvt.rn.f16x2.f32 %0, %1, %2;" : "=r"(wh) : "f"(s1), "f"(s0));
        float f0 = __half2float(__ushort_as_half((unsigned short)(wh & 0xffffu)));
        float f1 = __half2float(__ushort_as_half((unsigned short)(wh >> 16)));
        float e0 = s0 - f0, e1 = s1 - f1;
        unsigned wl;
        asm("cvt.rn.f16x2.f32 %0, %1, %2;" : "=r"(wl) : "f"(e1), "f"(e0));
        g_Mhi[((size_t)b * 64 + kh) * 128 + m] = wh;
        g_Mlo[((size_t)b * 64 + kh) * 128 + m] = wl;
    }
}

// ---- k4: out[b] = M @ X, fp16 2-product (Mhi+Mlo split, X single fp16) ----
// 144 CTAs = 8 b x 18 slices, 512 thr (16 warps 4x4, 32x32 warp tile).
#define KH_STRIDE 136
#define MS_WORDS  (64 * KH_STRIDE)

#define MMA_F16(d, a, bfr)                                             \
    asm volatile(                                                      \
        "mma.sync.aligned.m16n8k16.row.col.f32.f16.f16.f32 "           \
        "{%0,%1,%2,%3}, {%4,%5,%6,%7}, {%8,%9}, {%0,%1,%2,%3};"        \
        : "+f"(d[0]), "+f"(d[1]), "+f"(d[2]), "+f"(d[3])               \
        : "r"(a[0]), "r"(a[1]), "r"(a[2]), "r"(a[3]),                  \
          "r"(bfr[0]), "r"(bfr[1]))

__global__ __launch_bounds__(512, 1) void k4_gemm(const float* __restrict__ x,
                                                  float* __restrict__ out)
{
    extern __shared__ unsigned smu[];
    unsigned* Mh = smu;
    unsigned* Ml = smu + MS_WORDS;
    unsigned* Xh = smu + 2 * MS_WORDS;

    int b     = blockIdx.x & 7;
    int slice = blockIdx.x >> 3;  // 0..17
    int tid   = threadIdx.x;

    for (int idx = tid; idx < 8192; idx += 512) {
        int kh = idx >> 7, m = idx & 127;
        Mh[kh * KH_STRIDE + m] = g_Mhi[(size_t)b * 8192 + idx];
        Ml[kh * KH_STRIDE + m] = g_Mlo[(size_t)b * 8192 + idx];
    }

    const float* xb = x   + (size_t)b * 128 * 65536;
    float*       ob = out + (size_t)b * 128 * 65536;

    int khs  = tid >> 3;          // staged k-pair row 0..63
    int nseg = (tid & 7) << 4;    // staged n offset
    int w    = tid >> 5;
    int lane = tid & 31;
    int wm = (w & 3) * 32, wn = (w >> 2) * 32;
    int l4 = lane >> 2, lm = lane & 3;

    float4 r0[4], r1[4];
    int t = slice;
    {
        const float* p0 = xb + (size_t)(2 * khs) * 65536 + t * 128 + nseg;
        const float* p1 = p0 + 65536;
#pragma unroll
        for (int j = 0; j < 4; j++) { r0[j] = *(const float4*)(p0 + 4 * j);
                                      r1[j] = *(const float4*)(p1 + 4 * j); }
    }

    for (; t < 512; t += 18) {
        unsigned* dh = Xh + khs * KH_STRIDE + nseg;
#pragma unroll
        for (int j = 0; j < 4; j++) {
            const float* e0 = (const float*)&r0[j];
            const float* e1 = (const float*)&r1[j];
#pragma unroll
            for (int e = 0; e < 4; e++) {
                unsigned wv;  // lo = h(x@k even), hi = h(x@k odd)
                asm("cvt.rn.f16x2.f32 %0, %1, %2;" : "=r"(wv) : "f"(e1[e]), "f"(e0[e]));
                dh[4 * j + e] = wv;
            }
        }
        __syncthreads();

        if (t + 18 < 512) {  // prefetch next X tile (LDGs fly over MMA section)
            const float* p0 = xb + (size_t)(2 * khs) * 65536 + (t + 18) * 128 + nseg;
            const float* p1 = p0 + 65536;
#pragma unroll
            for (int j = 0; j < 4; j++) { r0[j] = *(const float4*)(p0 + 4 * j);
                                          r1[j] = *(const float4*)(p1 + 4 * j); }
        }

        float acc[2][4][4];
#pragma unroll
        for (int mi = 0; mi < 2; mi++)
#pragma unroll
            for (int ni = 0; ni < 4; ni++)
#pragma unroll
                for (int e = 0; e < 4; e++) acc[mi][ni][e] = 0.f;

#pragma unroll
        for (int ks = 0; ks < 8; ks++) {
            int r0a = (ks * 8 + lm) * KH_STRIDE;
            int r1a = r0a + 4 * KH_STRIDE;
            unsigned ah[2][4], al_[2][4];
#pragma unroll
            for (int mi = 0; mi < 2; mi++) {
                int colA = wm + 16 * mi + l4;
                ah[mi][0]  = Mh[r0a + colA];  ah[mi][1]  = Mh[r0a + colA + 8];
                ah[mi][2]  = Mh[r1a + colA];  ah[mi][3]  = Mh[r1a + colA + 8];
                al_[mi][0] = Ml[r0a + colA];  al_[mi][1] = Ml[r0a + colA + 8];
                al_[mi][2] = Ml[r1a + colA];  al_[mi][3] = Ml[r1a + colA + 8];
            }
            unsigned bh[4][2];
#pragma unroll
            for (int ni = 0; ni < 4; ni++) {
                int colB = wn + 8 * ni + l4;
                bh[ni][0] = Xh[r0a + colB];  bh[ni][1] = Xh[r1a + colB];
            }
#pragma unroll
            for (int mi = 0; mi < 2; mi++)
#pragma unroll
                for (int ni = 0; ni < 4; ni++) {
                    MMA_F16(acc[mi][ni], ah[mi],  bh[ni]);
                    MMA_F16(acc[mi][ni], al_[mi], bh[ni]);
                }
        }

#pragma unroll
        for (int mi = 0; mi < 2; mi++) {
            int row = wm + 16 * mi + l4;
#pragma unroll
            for (int ni = 0; ni < 4; ni++) {
                int col = t * 128 + wn + 8 * ni + 2 * lm;
                float2 v0 = {acc[mi][ni][0], acc[mi][ni][1]};
                float2 v1 = {acc[mi][ni][2], acc[mi][ni][3]};
                *(float2*)(ob + (size_t)row * 65536 + col)       = v0;
                *(float2*)(ob + (size_t)(row + 8) * 65536 + col) = v1;
            }
        }
        __syncthreads();
    }
}

// ---------------------------------------------------------------------------
extern "C" void kernel_launch(void* const* d_in, const int* in_sizes, int n_in,
                              void* d_out, int out_size)
{
    const float* x  = (const float*)d_in[0];
    const float* w1 = (const float*)d_in[1];
    const float* g1 = (const float*)d_in[2];
    const float* b1 = (const float*)d_in[3];
    const float* m1 = (const float*)d_in[4];
    const float* v1 = (const float*)d_in[5];
    const float* a1 = (const float*)d_in[6];
    const float* w2 = (const float*)d_in[7];
    const float* g2 = (const float*)d_in[8];
    const float* b2 = (const float*)d_in[9];
    const float* m2 = (const float*)d_in[10];
    const float* v2 = (const float*)d_in[11];
    const float* a2 = (const float*)d_in[12];
    float* out = (float*)d_out;

    const int SM1 = (XS_H * XS_W + 65 * P1_W) * 4;
    const int SM2 = 256 * PS_STRIDE * 4;
    const int SM4 = 3 * MS_WORDS * 4;   // 104448
    static bool attr_done = false;
    if (!attr_done) {
        cudaFuncSetAttribute(k1_pool, cudaFuncAttributeMaxDynamicSharedMemorySize, SM1);
        cudaFuncSetAttribute(k2_gram, cudaFuncAttributeMaxDynamicSharedMemorySize, SM2);
        cudaFuncSetAttribute(k4_gemm, cudaFuncAttributeMaxDynamicSharedMemorySize, SM4);
        attr_done = true;
    }

    k1_pool<<<dim3(1024, 4), 256, SM1>>>(x, w1, g1, b1, m1, v1, a1,
                                         w2, g2, b2, m2, v2, a2);
    k2_gram<<<128, 256, SM2>>>();
    k3_softmax<<<dim3(8, 16), 256>>>();
    k3b_pack<<<dim3(8, 4), 256>>>();
    k4_gemm<<<144, 512, SM4>>>(x, out);
}

// round 12
// speedup vs baseline: 1.1842x; 1.0337x over previous
#include <cuda_runtime.h>
#include <cuda_bf16.h>
#include <cuda_fp16.h>
#include <cstdint>

// scratch
__device__ float    g_p2[8 * 128 * 4096];
__device__ float    g_Gpart[16 * 8 * 128 * 128];
__device__ float    g_sim[8 * 128 * 128];
__device__ unsigned g_M2[8 * 8192];   // M=sim^T fp16, A-fragment-ordered

// ---- k1: fused (dwconv3x3 s2 -> BN -> PReLU) x2 ----
#define XS_H 131
#define XS_W 132
#define P1_W 66

__global__ __launch_bounds__(256) void k1_pool(
    const float* __restrict__ x,
    const float* __restrict__ w1, const float* __restrict__ g1, const float* __restrict__ b1,
    const float* __restrict__ m1, const float* __restrict__ v1, const float* __restrict__ a1_,
    const float* __restrict__ w2, const float* __restrict__ g2, const float* __restrict__ b2,
    const float* __restrict__ m2, const float* __restrict__ v2, const float* __restrict__ a2_)
{
    extern __shared__ float sm1[];
    float* xs  = sm1;
    float* p1s = sm1 + XS_H * XS_W;

    int bc = blockIdx.x, c = bc & 127, tid = threadIdx.x;
    int oy = (blockIdx.y >> 1) * 32, ox = (blockIdx.y & 1) * 32;

    float w1r[9], w2r[9];
#pragma unroll
    for (int i = 0; i < 9; i++) { w1r[i] = w1[c * 9 + i]; w2r[i] = w2[c * 9 + i]; }
    float s1 = g1[c] * rsqrtf(v1[c] + 1e-5f), t1 = b1[c] - m1[c] * s1, al1 = a1_[c];
    float s2 = g2[c] * rsqrtf(v2[c] + 1e-5f), t2 = b2[c] - m2[c] * s2, al2 = a2_[c];

    const float* xc = x + (size_t)bc * 65536;
    int gr0 = 4 * oy - 3, gc0 = 4 * ox - 3;
    for (int idx = tid; idx < XS_H * 131; idx += 256) {
        int r = idx / 131, cc = idx % 131;
        int gr = gr0 + r, gc = gc0 + cc;
        float v = 0.f;
        if ((unsigned)gr < 256u && (unsigned)gc < 256u) v = xc[gr * 256 + gc];
        xs[r * XS_W + cc] = v;
    }
    __syncthreads();

    for (int idx = tid; idx < 65 * 65; idx += 256) {
        int j = idx / 65, i = idx % 65;
        int r1 = 2 * oy - 1 + j, c1 = 2 * ox - 1 + i;
        float v = 0.f;
        if ((unsigned)r1 < 128u && (unsigned)c1 < 128u) {
            const float* xr = xs + (2 * j) * XS_W + 2 * i;
            float acc = 0.f;
#pragma unroll
            for (int dy = 0; dy < 3; dy++)
#pragma unroll
                for (int dx = 0; dx < 3; dx++)
                    acc += w1r[dy * 3 + dx] * xr[dy * XS_W + dx];
            v = acc * s1 + t1;
            v = v > 0.f ? v : al1 * v;
        }
        p1s[j * P1_W + i] = v;
    }
    __syncthreads();

    float* outp = g_p2 + (size_t)bc * 4096;
    for (int idx = tid; idx < 32 * 32; idx += 256) {
        int j = idx >> 5, i = idx & 31;
        const float* pr = p1s + (2 * j) * P1_W + 2 * i;
        float acc = 0.f;
#pragma unroll
        for (int dy = 0; dy < 3; dy++)
#pragma unroll
            for (int dx = 0; dx < 3; dx++)
                acc += w2r[dy * 3 + dx] * pr[dy * P1_W + dx];
        float v = acc * s2 + t2;
        v = v > 0.f ? v : al2 * v;
        outp[(oy + j) * 64 + (ox + i)] = v;
    }
}

// ---- k2: Gram partials ----
#define PS_STRIDE 136
__global__ __launch_bounds__(256) void k2_gram()
{
    extern __shared__ float ps[];
    int b = blockIdx.x & 7, ch = blockIdx.x >> 3, n0 = ch * 256, tid = threadIdx.x;
    const float* pb = g_p2 + (size_t)b * 128 * 4096;

    for (int v = tid; v < 128 * 64; v += 256) {
        int c = v >> 6, q = (v & 63) << 2;
        float4 f = *(const float4*)(pb + c * 4096 + n0 + q);
        ps[(q + 0) * PS_STRIDE + c] = f.x;
        ps[(q + 1) * PS_STRIDE + c] = f.y;
        ps[(q + 2) * PS_STRIDE + c] = f.z;
        ps[(q + 3) * PS_STRIDE + c] = f.w;
    }
    __syncthreads();

    int cb = (tid >> 4) * 8, kb = (tid & 15) * 8;
    float acc[8][8];
#pragma unroll
    for (int i = 0; i < 8; i++)
#pragma unroll
        for (int j = 0; j < 8; j++) acc[i][j] = 0.f;

    for (int n = 0; n < 256; n++) {
        const float* row = ps + n * PS_STRIDE;
        float4 A0 = *(const float4*)(row + cb), A1 = *(const float4*)(row + cb + 4);
        float4 B0 = *(const float4*)(row + kb), B1 = *(const float4*)(row + kb + 4);
        float a[8]  = {A0.x, A0.y, A0.z, A0.w, A1.x, A1.y, A1.z, A1.w};
        float bb[8] = {B0.x, B0.y, B0.z, B0.w, B1.x, B1.y, B1.z, B1.w};
#pragma unroll
        for (int i = 0; i < 8; i++)
#pragma unroll
            for (int j = 0; j < 8; j++) acc[i][j] += a[i] * bb[j];
    }
    float* gp = g_Gpart + ((size_t)(ch * 8 + b) * 128) * 128;
#pragma unroll
    for (int i = 0; i < 8; i++) {
        float4 o0 = {acc[i][0], acc[i][1], acc[i][2], acc[i][3]};
        float4 o1 = {acc[i][4], acc[i][5], acc[i][6], acc[i][7]};
        *(float4*)(gp + (cb + i) * 128 + kb)     = o0;
        *(float4*)(gp + (cb + i) * 128 + kb + 4) = o1;
    }
}

// ---- k3: reduce + softmax ----
__global__ __launch_bounds__(256) void k3_softmax()
{
    int b = blockIdx.x, c = blockIdx.y * 8 + (threadIdx.x >> 5), lane = threadIdx.x & 31;
    float4 acc = make_float4(0.f, 0.f, 0.f, 0.f);
    for (int ch = 0; ch < 16; ch++) {
        float4 g = *(const float4*)(g_Gpart + ((size_t)(ch * 8 + b) * 128 + c) * 128 + lane * 4);
        acc.x += g.x; acc.y += g.y; acc.z += g.z; acc.w += g.w;
    }
    const float s = 0.015625f;
    float lx = acc.x * s, ly = acc.y * s, lz = acc.z * s, lw = acc.w * s;
    float mx = fmaxf(fmaxf(lx, ly), fmaxf(lz, lw));
#pragma unroll
    for (int o = 16; o; o >>= 1) mx = fmaxf(mx, __shfl_xor_sync(0xffffffffu, mx, o));
    float ex = expf(lx - mx), ey = expf(ly - mx), ez = expf(lz - mx), ew = expf(lw - mx);
    float sum = ex + ey + ez + ew;
#pragma unroll
    for (int o = 16; o; o >>= 1) sum += __shfl_xor_sync(0xffffffffu, sum, o);
    float inv = 1.0f / sum;
    float4 o4 = make_float4(ex * inv, ey * inv, ez * inv, ew * inv);
    *(float4*)(g_sim + ((size_t)b * 128 + c) * 128 + lane * 4) = o4;
}

// ---- k3b: pack M into A-fragment-ordered fp16 words ----
// g_M2[b][ks][cg][lane][word]: word0:(kh=ks*8+lm, m=cg*16+l4) word1:(kh, m+8)
//                             word2:(kh+4, m)                word3:(kh+4, m+8)
// value = f16x2{ sim[2kh][m] (lo), sim[2kh+1][m] (hi) }
__global__ __launch_bounds__(256) void k3b_pack()
{
    int b = blockIdx.x, i0 = blockIdx.y * 2048;
    for (int idx = i0 + threadIdx.x; idx < i0 + 2048; idx += 256) {
        int word = idx & 3, lane = (idx >> 2) & 31, cg = (idx >> 7) & 7, ks = idx >> 10;
        int lm = lane & 3, l4 = lane >> 2;
        int kh = ks * 8 + lm + ((word & 2) ? 4 : 0);
        int m  = cg * 16 + l4 + ((word & 1) ? 8 : 0);
        float s0 = g_sim[((size_t)b * 128 + 2 * kh)     * 128 + m];
        float s1 = g_sim[((size_t)b * 128 + 2 * kh + 1) * 128 + m];
        unsigned wv;
        asm("cvt.rn.f16x2.f32 %0, %1, %2;" : "=r"(wv) : "f"(s1), "f"(s0));
        g_M2[b * 8192 + idx] = wv;
    }
}

// ---- k4: out[b] = M @ X, single-product fp16, double-buffered X ----
// 144 CTAs = 8 b x 18 slices, 512 thr (16 warps 4x4, 32x32 warp tile).
// X smem: pair-rows rr = ks*4 + jm (32 rows), each row ROWW words:
//   word(rr, c, h) at rr*ROWW + c*2 + h ; h=0 -> k-subrow jm, h=1 -> jm+4.
#define ROWW 264
#define XBUF_WORDS (32 * ROWW)   // 8448

#define MMA_F16(d, a, bfr)                                             \
    asm volatile(                                                      \
        "mma.sync.aligned.m16n8k16.row.col.f32.f16.f16.f32 "           \
        "{%0,%1,%2,%3}, {%4,%5,%6,%7}, {%8,%9}, {%0,%1,%2,%3};"        \
        : "+f"(d[0]), "+f"(d[1]), "+f"(d[2]), "+f"(d[3])               \
        : "r"(a[0]), "r"(a[1]), "r"(a[2]), "r"(a[3]),                  \
          "r"(bfr[0]), "r"(bfr[1]))

__global__ __launch_bounds__(512, 1) void k4_gemm(const float* __restrict__ x,
                                                  float* __restrict__ out)
{
    extern __shared__ unsigned smu[];
    unsigned* Ms = smu;                 // 8192 words
    unsigned* Xb0 = smu + 8192;         // 2 x 8448 words

    int b     = blockIdx.x & 7;
    int slice = blockIdx.x >> 3;  // 0..17
    int tid   = threadIdx.x;

    for (int i = tid; i < 8192; i += 512) Ms[i] = g_M2[b * 8192 + i];

    const float* xb = x   + (size_t)b * 128 * 65536;
    float*       ob = out + (size_t)b * 128 * 65536;

    int khs  = tid >> 3;          // k-pair row 0..63
    int nseg = (tid & 7) << 4;    // staged c base
    int w    = tid >> 5;
    int lane = tid & 31;
    int wm = (w & 3) * 32, wn = (w >> 2) * 32;
    int l4 = lane >> 2, lm = lane & 3;

    int rr  = (khs >> 3) * 4 + (khs & 3);
    int hi  = (khs >> 2) & 1;
    unsigned sbase = (unsigned)(rr * ROWW + nseg * 2 + hi);

    const float* p0 = xb + (size_t)(2 * khs) * 65536 + nseg;
    const float* p1 = p0 + 65536;

    float4 r0[4], r1[4];
    {
        const float* q0 = p0 + (size_t)slice * 128;
        const float* q1 = p1 + (size_t)slice * 128;
#pragma unroll
        for (int j = 0; j < 4; j++) { r0[j] = *(const float4*)(q0 + 4 * j);
                                      r1[j] = *(const float4*)(q1 + 4 * j); }
    }

    int it = 0;
    for (int t = slice; t < 512; t += 18, it++) {
        unsigned* Xs = Xb0 + (it & 1) * XBUF_WORDS;
        // convert + STS (pair layout)
#pragma unroll
        for (int j = 0; j < 4; j++) {
            const float* e0 = (const float*)&r0[j];
            const float* e1 = (const float*)&r1[j];
#pragma unroll
            for (int e = 0; e < 4; e++) {
                unsigned wv;  // lo = h(x@k even), hi = h(x@k odd)
                asm("cvt.rn.f16x2.f32 %0, %1, %2;" : "=r"(wv) : "f"(e1[e]), "f"(e0[e]));
                Xs[sbase + (4 * j + e) * 2] = wv;
            }
        }
        __syncthreads();   // single barrier per iter (double-buffered)

        if (t + 18 < 512) {  // prefetch next X tile
            const float* q0 = p0 + (size_t)(t + 18) * 128;
            const float* q1 = p1 + (size_t)(t + 18) * 128;
#pragma unroll
            for (int j = 0; j < 4; j++) { r0[j] = *(const float4*)(q0 + 4 * j);
                                          r1[j] = *(const float4*)(q1 + 4 * j); }
        }

        float acc[2][4][4];
#pragma unroll
        for (int mi = 0; mi < 2; mi++)
#pragma unroll
            for (int ni = 0; ni < 4; ni++)
#pragma unroll
                for (int e = 0; e < 4; e++) acc[mi][ni][e] = 0.f;

#pragma unroll
        for (int ks = 0; ks < 8; ks++) {
            uint4 a0 = *(const uint4*)&Ms[ks * 1024 + ((w & 3) * 2 + 0) * 128 + lane * 4];
            uint4 a1 = *(const uint4*)&Ms[ks * 1024 + ((w & 3) * 2 + 1) * 128 + lane * 4];
            unsigned ah0[4] = {a0.x, a0.y, a0.z, a0.w};
            unsigned ah1[4] = {a1.x, a1.y, a1.z, a1.w};
            const unsigned* brow = Xs + (ks * 4 + lm) * ROWW;
            unsigned bh[4][2];
#pragma unroll
            for (int ni = 0; ni < 4; ni++) {
                uint2 bv = *(const uint2*)&brow[(wn + 8 * ni + l4) * 2];
                bh[ni][0] = bv.x; bh[ni][1] = bv.y;
            }
#pragma unroll
            for (int ni = 0; ni < 4; ni++) {
                MMA_F16(acc[0][ni], ah0, bh[ni]);
                MMA_F16(acc[1][ni], ah1, bh[ni]);
            }
        }

#pragma unroll
        for (int mi = 0; mi < 2; mi++) {
            int row = wm + 16 * mi + l4;
#pragma unroll
            for (int ni = 0; ni < 4; ni++) {
                int col = t * 128 + wn + 8 * ni + 2 * lm;
                float2 v0 = {acc[mi][ni][0], acc[mi][ni][1]};
                float2 v1 = {acc[mi][ni][2], acc[mi][ni][3]};
                *(float2*)(ob + (size_t)row * 65536 + col)       = v0;
                *(float2*)(ob + (size_t)(row + 8) * 65536 + col) = v1;
            }
        }
    }
}

// ---------------------------------------------------------------------------
extern "C" void kernel_launch(void* const* d_in, const int* in_sizes, int n_in,
                              void* d_out, int out_size)
{
    const float* x  = (const float*)d_in[0];
    const float* w1 = (const float*)d_in[1];
    const float* g1 = (const float*)d_in[2];
    const float* b1 = (const float*)d_in[3];
    const float* m1 = (const float*)d_in[4];
    const float* v1 = (const float*)d_in[5];
    const float* a1 = (const float*)d_in[6];
    const float* w2 = (const float*)d_in[7];
    const float* g2 = (const float*)d_in[8];
    const float* b2 = (const float*)d_in[9];
    const float* m2 = (const float*)d_in[10];
    const float* v2 = (const float*)d_in[11];
    const float* a2 = (const float*)d_in[12];
    float* out = (float*)d_out;

    const int SM1 = (XS_H * XS_W + 65 * P1_W) * 4;
    const int SM2 = 256 * PS_STRIDE * 4;
    const int SM4 = (8192 + 2 * XBUF_WORDS) * 4;   // 100352
    static bool attr_done = false;
    if (!attr_done) {
        cudaFuncSetAttribute(k1_pool, cudaFuncAttributeMaxDynamicSharedMemorySize, SM1);
        cudaFuncSetAttribute(k2_gram, cudaFuncAttributeMaxDynamicSharedMemorySize, SM2);
        cudaFuncSetAttribute(k4_gemm, cudaFuncAttributeMaxDynamicSharedMemorySize, SM4);
        attr_done = true;
    }

    k1_pool<<<dim3(1024, 4), 256, SM1>>>(x, w1, g1, b1, m1, v1, a1,
                                         w2, g2, b2, m2, v2, a2);
    k2_gram<<<128, 256, SM2>>>();
    k3_softmax<<<dim3(8, 16), 256>>>();
    k3b_pack<<<dim3(8, 4), 256>>>();
    k4_gemm<<<144, 512, SM4>>>(x, out);
}